// round 1
// baseline (speedup 1.0000x reference)
#include <cuda_runtime.h>

#define FULLMASK 0xffffffffu

// heuristic(cell) = (dx+dy) - min(dx,dy) + 0.001*sqrt(dx^2+dy^2)
// all distances are small integers (exact in fp32); force IEEE mul/add/sqrt so the
// rounding matches XLA's separate mul-then-add regardless of nvcc fast-math flags.
__device__ __forceinline__ float heur_part(int r, int c, int gr, int gc) {
    int d0 = r - gr; if (d0 < 0) d0 = -d0;
    int d1 = c - gc; if (d1 < 0) d1 = -d1;
    int mx = d0 > d1 ? d0 : d1;                 // sum - min == max, exactly
    float euc = __fsqrt_rn((float)(d0 * d0 + d1 * d1));
    return __fadd_rn((float)mx, __fmul_rn(0.001f, euc));
}

__global__ __launch_bounds__(128, 1)
void astar_kernel(const float* __restrict__ cost_all,
                  const float* __restrict__ start_all,
                  const float* __restrict__ goal_all,
                  const float* __restrict__ obst_all,
                  float* __restrict__ out)
{
    const int HW = 4096;
    const int STEPS = 409;           // int(0.1 * 64 * 64)
    const unsigned INFB = 0x7f800000u;  // +inf bits; uint compare == float compare for x>=0

    __shared__ float key[4096];          // f = 0.5*g + 0.5*h if open, +inf otherwise
    __shared__ float g_arr[4096];
    __shared__ unsigned short par[4096];
    __shared__ unsigned int smw[128], histw[128], obstw[128], pathw[128];
    __shared__ unsigned int rowmin[64];  // per-row min of key (as uint bits)
    __shared__ int s_goal, s_start, s_sel, s_solved;
    __shared__ float s_g2;

    const int b    = blockIdx.x;
    const int tid  = threadIdx.x;
    const int lane = tid & 31;
    const int wid  = tid >> 5;
    const float* cost = cost_all + b * HW;

    // ---------------- init ----------------
    for (int i = tid; i < HW; i += 128) {
        if (goal_all[b * HW + i]  > 0.5f) s_goal  = i;
        if (start_all[b * HW + i] > 0.5f) s_start = i;
        unsigned w = __ballot_sync(FULLMASK, obst_all[b * HW + i] > 0.5f);
        if (lane == 0) obstw[i >> 5] = w;
        key[i]   = __uint_as_float(INFB);
        g_arr[i] = 0.0f;
    }
    smw[tid] = 0u; histw[tid] = 0u; pathw[tid] = 0u;   // blockDim == 128 == word count
    if (tid < 64) rowmin[tid] = INFB;
    __syncthreads();

    const int goal_idx = s_goal;
    const int gr = goal_idx >> 6, gc = goal_idx & 63;
    for (int i = tid; i < HW; i += 128) par[i] = (unsigned short)goal_idx;

    if (tid == 0) {
        int st = s_start;
        smw[st >> 5] |= 1u << (st & 31);
        float h0 = __fadd_rn(heur_part(st >> 6, st & 63, gr, gc), cost[st]);
        float f0 = 0.5f * h0;            // g=0: f = 0 + 0.5*h, exact
        key[st] = f0;
        rowmin[st >> 6] = __float_as_uint(f0);
        s_solved = 0;
    }
    __syncthreads();

    // ---------------- main sequential search ----------------
    for (int step = 0; step < STEPS; ++step) {
        // Phase A (warp 0): global argmin with first-index tie-break
        if (wid == 0) {
            unsigned u0 = rowmin[lane], u1 = rowmin[lane + 32];
            unsigned m  = __reduce_min_sync(FULLMASK, u0 < u1 ? u0 : u1);
            unsigned b0 = __ballot_sync(FULLMASK, u0 == m);
            unsigned b1 = __ballot_sync(FULLMASK, u1 == m);
            int r = b0 ? (__ffs(b0) - 1) : (__ffs(b1) + 31);
            unsigned k0 = __float_as_uint(key[(r << 6) + lane]);
            unsigned k1 = __float_as_uint(key[(r << 6) + lane + 32]);
            unsigned c0 = __ballot_sync(FULLMASK, k0 == m);
            unsigned c1 = __ballot_sync(FULLMASK, k1 == m);
            int c = c0 ? (__ffs(c0) - 1) : (__ffs(c1) + 31);
            if (lane == 0) s_sel = (r << 6) + c;
        }
        __syncthreads();
        const int sel = s_sel;

        // Phase B (warp 0): select/close + expand 3x3 neighborhood
        if (wid == 0) {
            const int solved = (sel == goal_idx);
            if (lane == 0) {
                histw[sel >> 5] |= 1u << (sel & 31);
                if (!solved) {
                    smw[sel >> 5] &= ~(1u << (sel & 31));
                    key[sel] = __uint_as_float(INFB);
                }
                s_solved = solved;
                s_g2 = __fadd_rn(g_arr[sel], cost[sel]);
            }
            __syncwarp();
            // on solve, post-update state is provably a fixed point and the
            // neighbor updates cannot affect hist/path outputs -> skip & break.
            if (!solved && lane < 8) {
                int idx9 = lane + (lane >= 4 ? 1 : 0);      // 0..8 skipping center
                int nr = (sel >> 6) + idx9 / 3 - 1;
                int nc = (sel & 63) + idx9 % 3 - 1;
                if (nr >= 0 && nr < 64 && nc >= 0 && nc < 64) {
                    int n = (nr << 6) + nc;
                    unsigned bm = 1u << (n & 31);
                    if (obstw[n >> 5] & bm) {
                        bool smv = smw[n >> 5] & bm;
                        bool hv  = histw[n >> 5] & bm;
                        float g2v = s_g2;
                        if ((!smv && !hv) || (smv && g_arr[n] > g2v)) {
                            g_arr[n] = g2v;
                            float hn = __fadd_rn(heur_part(nr, nc, gr, gc), cost[n]);
                            key[n] = __fadd_rn(0.5f * g2v, 0.5f * hn);
                            par[n] = (unsigned short)sel;
                            atomicOr(&smw[n >> 5], bm);
                        }
                    }
                }
            }
        }
        __syncthreads();
        if (s_solved) break;

        // Phase C (warps 0-2): refresh row mins for the 3 touched rows
        int rr = (sel >> 6) - 1 + wid;
        if (wid < 3 && rr >= 0 && rr < 64) {
            unsigned a0 = __float_as_uint(key[(rr << 6) + lane]);
            unsigned a1 = __float_as_uint(key[(rr << 6) + lane + 32]);
            unsigned m  = __reduce_min_sync(FULLMASK, a0 < a1 ? a0 : a1);
            if (lane == 0) rowmin[rr] = m;
        }
        __syncthreads();
    }

    // ---------------- backtrack ----------------
    if (tid == 0) {
        pathw[goal_idx >> 5] |= 1u << (goal_idx & 31);
        int loc = par[goal_idx];
        if (s_solved) {
            // parent chain is a cycle goal->...->start->goal; t_stop >= path len,
            // so marking exactly one full cycle == reference's t_stop marks.
            int first = loc;
            #pragma unroll 1
            for (int i = 0; i < STEPS; ++i) {
                pathw[loc >> 5] |= 1u << (loc & 31);
                loc = par[loc];
                if (loc == first) break;
            }
        } else {
            // never all-solved -> t_stop == STEPS-1 exactly
            #pragma unroll 1
            for (int i = 0; i < STEPS - 1; ++i) {
                pathw[loc >> 5] |= 1u << (loc & 31);
                loc = par[loc];
            }
        }
    }
    __syncthreads();

    // ---------------- outputs: [hist (B,1,64,64)] then [path (B,1,64,64)] ----------------
    float* hist_out = out + b * HW;
    float* path_out = out + 16 * HW + b * HW;
    for (int i = tid; i < HW; i += 128) {
        hist_out[i] = ((histw[i >> 5] >> (i & 31)) & 1) ? 1.0f : 0.0f;
        path_out[i] = ((pathw[i >> 5] >> (i & 31)) & 1) ? 1.0f : 0.0f;
    }
}

extern "C" void kernel_launch(void* const* d_in, const int* in_sizes, int n_in,
                              void* d_out, int out_size) {
    const float* cost  = (const float*)d_in[0];
    const float* start = (const float*)d_in[1];
    const float* goal  = (const float*)d_in[2];
    const float* obst  = (const float*)d_in[3];
    astar_kernel<<<16, 128>>>(cost, start, goal, obst, (float*)d_out);
}

// round 4
// speedup vs baseline: 1.2149x; 1.2149x over previous
#include <cuda_runtime.h>

#define FULLMASK 0xffffffffu
#define INFB 0x7f800000u

// heuristic(cell) = max(dx,dy) + 0.001*sqrt(dx^2+dy^2)   (== (dx+dy)-min(dx,dy))
// IEEE ops so rounding matches XLA regardless of fast-math flags.
__device__ __forceinline__ float heur_part(int r, int c, int gr, int gc) {
    int d0 = r - gr; if (d0 < 0) d0 = -d0;
    int d1 = c - gc; if (d1 < 0) d1 = -d1;
    int mx = d0 > d1 ? d0 : d1;
    float euc = __fsqrt_rn((float)(d0 * d0 + d1 * d1));
    return __fadd_rn((float)mx, __fmul_rn(0.001f, euc));
}

// dynamic smem layout:
//  key   : 4096 f32  (f = 0.5g+0.5h if open, +inf otherwise)
//  g     : 4096 f32
//  keyh  : 4096 f32  (heur + cost, precomputed)
//  cost  : 4096 f32
//  par   : 4096 u16
//  obstw/smw/histw/pathw : 4 x 128 u32
#define SMEM_BYTES (4 * 4096 * 4 + 4096 * 2 + 4 * 128 * 4)

extern __shared__ unsigned char dynsmem[];

__global__ __launch_bounds__(128, 1)
void astar_kernel(const float* __restrict__ cost_all,
                  const float* __restrict__ start_all,
                  const float* __restrict__ goal_all,
                  const float* __restrict__ obst_all,
                  float* __restrict__ out)
{
    const int HW = 4096;
    const int STEPS = 409;               // int(0.1 * 64 * 64)

    float* key            = (float*)dynsmem;
    float* g_arr          = key   + 4096;
    float* keyh           = g_arr + 4096;
    float* cost_s         = keyh  + 4096;
    unsigned short* par   = (unsigned short*)(cost_s + 4096);
    unsigned* obstw       = (unsigned*)(par + 4096);
    unsigned* smw         = obstw + 128;
    unsigned* histw       = smw   + 128;
    unsigned* pathw       = histw + 128;

    __shared__ int s_goal, s_start;

    const int b    = blockIdx.x;
    const int tid  = threadIdx.x;
    const int lane = tid & 31;
    const int wid  = tid >> 5;

    // ---------------- init pass 1: locate start/goal, load cost/obstacles ----------------
    for (int i = tid; i < HW; i += 128) {
        if (goal_all[b * HW + i]  > 0.5f) s_goal  = i;
        if (start_all[b * HW + i] > 0.5f) s_start = i;
        unsigned w = __ballot_sync(FULLMASK, obst_all[b * HW + i] > 0.5f);
        if (lane == 0) obstw[i >> 5] = w;
        cost_s[i] = cost_all[b * HW + i];
        key[i]    = __uint_as_float(INFB);
        g_arr[i]  = 0.0f;
    }
    smw[tid] = 0u; histw[tid] = 0u; pathw[tid] = 0u;   // blockDim == word count
    __syncthreads();

    const int goal_idx = s_goal;
    const int start_idx = s_start;
    const int gr = goal_idx >> 6, gc = goal_idx & 63;

    // ---------------- init pass 2: precompute keyh, parents ----------------
    for (int i = tid; i < HW; i += 128) {
        keyh[i] = __fadd_rn(heur_part(i >> 6, i & 63, gr, gc), cost_s[i]);
        par[i]  = (unsigned short)goal_idx;
    }
    __syncthreads();

    // ---------------- single-warp sequential search ----------------
    if (wid == 0) {
        // open the start cell
        unsigned rm0 = INFB, rm1 = INFB;            // per-row mins: lane owns rows lane, lane+32
        {
            float f0 = 0.5f * keyh[start_idx];       // g=0: exact
            if (lane == 0) {
                key[start_idx] = f0;
                smw[start_idx >> 5] |= 1u << (start_idx & 31);
            }
            int srow = start_idx >> 6;
            if (lane == (srow & 31)) {
                if (srow < 32) rm0 = __float_as_uint(f0);
                else           rm1 = __float_as_uint(f0);
            }
        }
        __syncwarp();

        for (int step = 0; step < STEPS; ++step) {
            // ---- A: global argmin with first-flat-index tie-break (registers + row scan)
            unsigned m  = __reduce_min_sync(FULLMASK, rm0 < rm1 ? rm0 : rm1);
            unsigned b0 = __ballot_sync(FULLMASK, rm0 == m);
            unsigned b1 = __ballot_sync(FULLMASK, rm1 == m);
            int r = b0 ? (__ffs(b0) - 1) : (__ffs(b1) + 31);
            unsigned k0 = __float_as_uint(key[(r << 6) + lane]);
            unsigned k1 = __float_as_uint(key[(r << 6) + 32 + lane]);
            unsigned c0 = __ballot_sync(FULLMASK, k0 == m);
            unsigned c1 = __ballot_sync(FULLMASK, k1 == m);
            int c = c0 ? (__ffs(c0) - 1) : (__ffs(c1) + 31);
            const int sel = (r << 6) + c;

            // ---- B: close + expand
            if (lane == 0)
                histw[sel >> 5] |= 1u << (sel & 31);       // only writer of histw
            if (sel == goal_idx) break;                     // solve step: expansion provably
                                                            // cannot affect hist/path outputs
            if (lane == 0) {
                atomicAnd(&smw[sel >> 5], ~(1u << (sel & 31)));
                key[sel] = __uint_as_float(INFB);
            }
            float g2 = __fadd_rn(g_arr[sel], cost_s[sel]);  // uniform broadcast loads

            unsigned kb = INFB; int nrow = -1;
            if (lane < 8) {
                int idx9 = lane + (lane >= 4);              // 0..8 skipping center
                int nr = r + idx9 / 3 - 1;
                int nc = c + idx9 % 3 - 1;
                if (nr >= 0 && nr < 64 && nc >= 0 && nc < 64) {
                    int n = (nr << 6) + nc;
                    unsigned bm = 1u << (n & 31);
                    if (obstw[n >> 5] & bm) {
                        bool smv = smw[n >> 5] & bm;
                        bool hv  = histw[n >> 5] & bm;
                        if ((!smv && !hv) || (smv && g_arr[n] > g2)) {
                            g_arr[n] = g2;
                            float kn = __fadd_rn(0.5f * g2, 0.5f * keyh[n]);
                            key[n] = kn;
                            par[n] = (unsigned short)sel;
                            atomicOr(&smw[n >> 5], bm);
                            if (nr != r) { kb = __float_as_uint(kn); nrow = nr; }
                        }
                    }
                }
            }
            // fold new keys (only ever decreases) into rows r-1 / r+1 owner registers
            unsigned vup = (nrow == r - 1) ? kb : INFB;
            unsigned vdn = (nrow == r + 1) ? kb : INFB;
            unsigned mup = __reduce_min_sync(FULLMASK, vup);
            unsigned mdn = __reduce_min_sync(FULLMASK, vdn);
            {
                int ru = r - 1;
                if (ru >= 0 && lane == (ru & 31)) {
                    if (ru < 32) { if (mup < rm0) rm0 = mup; }
                    else         { if (mup < rm1) rm1 = mup; }
                }
                int rd = r + 1;
                if (rd < 64 && lane == (rd & 31)) {
                    if (rd < 32) { if (mdn < rm0) rm0 = mdn; }
                    else         { if (mdn < rm1) rm1 = mdn; }
                }
            }
            __syncwarp();

            // ---- C: full recompute of sel's row only (key[sel] went to +inf)
            unsigned a0 = __float_as_uint(key[(r << 6) + lane]);
            unsigned a1 = __float_as_uint(key[(r << 6) + 32 + lane]);
            unsigned mr = __reduce_min_sync(FULLMASK, a0 < a1 ? a0 : a1);
            if (lane == (r & 31)) {
                if (r < 32) rm0 = mr; else rm1 = mr;
            }
        }

        // ---- backtrack (lane 0): deterministic chase repeats after any revisit,
        // so stop at the first already-marked node; cap 408 == reference t_stop bound.
        if (lane == 0) {
            pathw[goal_idx >> 5] |= 1u << (goal_idx & 31);
            int loc = par[goal_idx];
            #pragma unroll 1
            for (int i = 0; i < STEPS - 1; ++i) {
                unsigned bm = 1u << (loc & 31);
                if (pathw[loc >> 5] & bm) break;
                pathw[loc >> 5] |= bm;
                loc = par[loc];
            }
        }
    }
    __syncthreads();

    // ---------------- outputs: hist (B,1,64,64) then path (B,1,64,64) ----------------
    float* hist_out = out + b * HW;
    float* path_out = out + 16 * HW + b * HW;
    for (int i = tid; i < HW; i += 128) {
        hist_out[i] = ((histw[i >> 5] >> (i & 31)) & 1) ? 1.0f : 0.0f;
        path_out[i] = ((pathw[i >> 5] >> (i & 31)) & 1) ? 1.0f : 0.0f;
    }
}

extern "C" void kernel_launch(void* const* d_in, const int* in_sizes, int n_in,
                              void* d_out, int out_size) {
    const float* cost  = (const float*)d_in[0];
    const float* start = (const float*)d_in[1];
    const float* goal  = (const float*)d_in[2];
    const float* obst  = (const float*)d_in[3];
    cudaFuncSetAttribute(astar_kernel,
                         cudaFuncAttributeMaxDynamicSharedMemorySize, SMEM_BYTES);
    astar_kernel<<<16, 128, SMEM_BYTES>>>(cost, start, goal, obst, (float*)d_out);
}

// round 6
// speedup vs baseline: 1.3372x; 1.1007x over previous
#include <cuda_runtime.h>

#define FULLMASK 0xffffffffu
#define INFB 0x7f800000u

// heuristic(cell) = max(dx,dy) + 0.001*sqrt(dx^2+dy^2)   (== (dx+dy)-min(dx,dy))
// IEEE ops so rounding matches XLA regardless of fast-math flags.
__device__ __forceinline__ float heur_part(int r, int c, int gr, int gc) {
    int d0 = r - gr; if (d0 < 0) d0 = -d0;
    int d1 = c - gc; if (d1 < 0) d1 = -d1;
    int mx = d0 > d1 ? d0 : d1;
    float euc = __fsqrt_rn((float)(d0 * d0 + d1 * d1));
    return __fadd_rn((float)mx, __fmul_rn(0.001f, euc));
}

// dynamic smem layout:
//  key   : 4096 f32  (f = 0.5g+0.5h if open, +inf otherwise)
//  g     : 4096 f32
//  keyh  : 4096 f32  (heur + cost, precomputed)
//  cost  : 4096 f32
//  par   : 4096 u16
//  obstw/smw/histw/pathw : 4 x 128 u32
#define SMEM_BYTES (4 * 4096 * 4 + 4096 * 2 + 4 * 128 * 4)

extern __shared__ unsigned char dynsmem[];

__global__ __launch_bounds__(128, 1)
void astar_kernel(const float* __restrict__ cost_all,
                  const float* __restrict__ start_all,
                  const float* __restrict__ goal_all,
                  const float* __restrict__ obst_all,
                  float* __restrict__ out)
{
    const int HW = 4096;
    const int STEPS = 409;               // int(0.1 * 64 * 64)

    float* key            = (float*)dynsmem;
    float* g_arr          = key   + 4096;
    float* keyh           = g_arr + 4096;
    float* cost_s         = keyh  + 4096;
    unsigned short* par   = (unsigned short*)(cost_s + 4096);
    unsigned* obstw       = (unsigned*)(par + 4096);
    unsigned* smw         = obstw + 128;
    unsigned* histw       = smw   + 128;
    unsigned* pathw       = histw + 128;

    __shared__ int s_goal, s_start;

    const int b    = blockIdx.x;
    const int tid  = threadIdx.x;
    const int lane = tid & 31;
    const int wid  = tid >> 5;

    // ---------------- init: zero bit words, then vectorized pass 1 ----------------
    obstw[tid] = 0u; smw[tid] = 0u; histw[tid] = 0u; pathw[tid] = 0u;
    __syncthreads();

    {
        const float4* cost4  = (const float4*)(cost_all  + b * HW);
        const float4* start4 = (const float4*)(start_all + b * HW);
        const float4* goal4  = (const float4*)(goal_all  + b * HW);
        const float4* obst4  = (const float4*)(obst_all  + b * HW);
        float4* cost_s4 = (float4*)cost_s;
        float4* key4    = (float4*)key;
        float4* g4      = (float4*)g_arr;
        const float inf = __uint_as_float(INFB);
        for (int i4 = tid; i4 < 1024; i4 += 128) {
            int base = i4 << 2;
            float4 gl = goal4[i4], st = start4[i4], ob = obst4[i4];
            if (gl.x > 0.5f) s_goal = base;     if (gl.y > 0.5f) s_goal = base + 1;
            if (gl.z > 0.5f) s_goal = base + 2; if (gl.w > 0.5f) s_goal = base + 3;
            if (st.x > 0.5f) s_start = base;     if (st.y > 0.5f) s_start = base + 1;
            if (st.z > 0.5f) s_start = base + 2; if (st.w > 0.5f) s_start = base + 3;
            unsigned nib = (ob.x > 0.5f ? 1u : 0u) | (ob.y > 0.5f ? 2u : 0u)
                         | (ob.z > 0.5f ? 4u : 0u) | (ob.w > 0.5f ? 8u : 0u);
            atomicOr(&obstw[base >> 5], nib << (base & 31));
            cost_s4[i4] = cost4[i4];
            key4[i4]    = make_float4(inf, inf, inf, inf);
            g4[i4]      = make_float4(0.f, 0.f, 0.f, 0.f);
        }
    }
    __syncthreads();

    const int goal_idx  = s_goal;
    const int start_idx = s_start;
    const int gr = goal_idx >> 6, gc = goal_idx & 63;

    // ---------------- init pass 2: precompute keyh, parents ----------------
    {
        float4*  keyh4 = (float4*)keyh;
        ushort4* par4  = (ushort4*)par;
        const unsigned short gp = (unsigned short)goal_idx;
        for (int i4 = tid; i4 < 1024; i4 += 128) {
            int base = i4 << 2;
            float4 cv = ((const float4*)cost_s)[i4];
            float4 kh;
            kh.x = __fadd_rn(heur_part(base >> 6, base & 63, gr, gc), cv.x);
            kh.y = __fadd_rn(heur_part((base + 1) >> 6, (base + 1) & 63, gr, gc), cv.y);
            kh.z = __fadd_rn(heur_part((base + 2) >> 6, (base + 2) & 63, gr, gc), cv.z);
            kh.w = __fadd_rn(heur_part((base + 3) >> 6, (base + 3) & 63, gr, gc), cv.w);
            keyh4[i4] = kh;
            par4[i4]  = make_ushort4(gp, gp, gp, gp);
        }
    }
    __syncthreads();

    // ---------------- single-warp sequential search ----------------
    if (wid == 0) {
        // open the start cell
        unsigned rm0 = INFB, rm1 = INFB;            // per-row mins: lane owns rows lane, lane+32
        {
            float f0 = 0.5f * keyh[start_idx];       // g=0: exact
            if (lane == 0) {
                key[start_idx] = f0;
                smw[start_idx >> 5] |= 1u << (start_idx & 31);
            }
            int srow = start_idx >> 6;
            if (lane == (srow & 31)) {
                if (srow < 32) rm0 = __float_as_uint(f0);
                else           rm1 = __float_as_uint(f0);
            }
        }
        __syncwarp();

        for (int step = 0; step < STEPS; ++step) {
            // ---- A: global argmin with first-flat-index tie-break
            unsigned m  = __reduce_min_sync(FULLMASK, rm0 < rm1 ? rm0 : rm1);
            unsigned b0 = __ballot_sync(FULLMASK, rm0 == m);
            unsigned b1 = __ballot_sync(FULLMASK, rm1 == m);
            int r = b0 ? (__ffs(b0) - 1) : (__ffs(b1) + 31);
            unsigned k0 = __float_as_uint(key[(r << 6) + lane]);
            unsigned k1 = __float_as_uint(key[(r << 6) + 32 + lane]);
            unsigned c0 = __ballot_sync(FULLMASK, k0 == m);
            unsigned c1 = __ballot_sync(FULLMASK, k1 == m);
            int c = c0 ? (__ffs(c0) - 1) : (__ffs(c1) + 31);
            const int sel = (r << 6) + c;

            // ---- B: close + expand
            if (lane == 0)
                histw[sel >> 5] |= 1u << (sel & 31);       // only writer of histw
            if (sel == goal_idx) break;                     // solve step: expansion provably
                                                            // cannot affect hist/path outputs
            if (lane == 0) {
                atomicAnd(&smw[sel >> 5], ~(1u << (sel & 31)));
                key[sel] = __uint_as_float(INFB);
            }
            float g2 = __fadd_rn(g_arr[sel], cost_s[sel]);  // uniform broadcast loads

            unsigned kb = INFB; int nrow = -99;
            if (lane < 8) {
                int idx9 = lane + (lane >= 4);              // 0..8 skipping center
                int nr = r + idx9 / 3 - 1;
                int nc = c + idx9 % 3 - 1;
                if (nr >= 0 && nr < 64 && nc >= 0 && nc < 64) {
                    int n = (nr << 6) + nc;
                    unsigned bm = 1u << (n & 31);
                    if (obstw[n >> 5] & bm) {
                        bool smv = smw[n >> 5] & bm;
                        bool hv  = histw[n >> 5] & bm;
                        if ((!smv && !hv) || (smv && g_arr[n] > g2)) {
                            g_arr[n] = g2;
                            float kn = __fadd_rn(0.5f * g2, 0.5f * keyh[n]);
                            key[n] = kn;
                            par[n] = (unsigned short)sel;
                            atomicOr(&smw[n >> 5], bm);
                            kb = __float_as_uint(kn); nrow = nr;   // updates only DECREASE keys
                        }
                    }
                }
            }
            // ---- C (register-only): three independent reduxes, fully overlapped.
            // rows r-1 / r+1: fold-in (monotone decrease). row r: exact recompute from
            // phase-A registers with sel masked out + same-row new keys (stale values
            // are safe overestimates for updated cells).
            unsigned vup = (nrow == r - 1) ? kb : INFB;
            unsigned vdn = (nrow == r + 1) ? kb : INFB;
            unsigned vrw = (nrow == r)     ? kb : INFB;
            unsigned mk0 = (c < 32  && lane == c)        ? INFB : k0;
            unsigned mk1 = (c >= 32 && lane == (c - 32)) ? INFB : k1;
            unsigned mrv = mk0 < mk1 ? mk0 : mk1;
            mrv = mrv < vrw ? mrv : vrw;
            unsigned mup  = __reduce_min_sync(FULLMASK, vup);
            unsigned mdn  = __reduce_min_sync(FULLMASK, vdn);
            unsigned mrow = __reduce_min_sync(FULLMASK, mrv);
            if (r > 0 && lane == ((r - 1) & 31)) {
                if (r - 1 < 32) { if (mup < rm0) rm0 = mup; }
                else            { if (mup < rm1) rm1 = mup; }
            }
            if (r < 63 && lane == ((r + 1) & 31)) {
                if (r + 1 < 32) { if (mdn < rm0) rm0 = mdn; }
                else            { if (mdn < rm1) rm1 = mdn; }
            }
            if (lane == (r & 31)) {
                if (r < 32) rm0 = mrow; else rm1 = mrow;
            }
            __syncwarp();   // order this step's STS before next step's key-row LDS
        }

        // ---- backtrack (lane 0): deterministic chase repeats after any revisit,
        // so stop at the first already-marked node; cap 408 == reference t_stop bound.
        if (lane == 0) {
            pathw[goal_idx >> 5] |= 1u << (goal_idx & 31);
            int loc = par[goal_idx];
            #pragma unroll 1
            for (int i = 0; i < STEPS - 1; ++i) {
                unsigned bm = 1u << (loc & 31);
                if (pathw[loc >> 5] & bm) break;
                pathw[loc >> 5] |= bm;
                loc = par[loc];
            }
        }
    }
    __syncthreads();

    // ---------------- outputs: hist (B,1,64,64) then path (B,1,64,64) ----------------
    {
        float4* hist4 = (float4*)(out + b * HW);
        float4* path4 = (float4*)(out + 16 * HW + b * HW);
        for (int i4 = tid; i4 < 1024; i4 += 128) {
            int base = i4 << 2;
            unsigned hw = histw[base >> 5] >> (base & 31);
            unsigned pw = pathw[base >> 5] >> (base & 31);
            hist4[i4] = make_float4((hw & 1) ? 1.f : 0.f, (hw & 2) ? 1.f : 0.f,
                                    (hw & 4) ? 1.f : 0.f, (hw & 8) ? 1.f : 0.f);
            path4[i4] = make_float4((pw & 1) ? 1.f : 0.f, (pw & 2) ? 1.f : 0.f,
                                    (pw & 4) ? 1.f : 0.f, (pw & 8) ? 1.f : 0.f);
        }
    }
}

extern "C" void kernel_launch(void* const* d_in, const int* in_sizes, int n_in,
                              void* d_out, int out_size) {
    const float* cost  = (const float*)d_in[0];
    const float* start = (const float*)d_in[1];
    const float* goal  = (const float*)d_in[2];
    const float* obst  = (const float*)d_in[3];
    cudaFuncSetAttribute(astar_kernel,
                         cudaFuncAttributeMaxDynamicSharedMemorySize, SMEM_BYTES);
    astar_kernel<<<16, 128, SMEM_BYTES>>>(cost, start, goal, obst, (float*)d_out);
}

// round 7
// speedup vs baseline: 1.3481x; 1.0082x over previous
#include <cuda_runtime.h>

#define FULLMASK 0xffffffffu
#define INFB 0x7f800000u

// heuristic(cell) = max(dx,dy) + 0.001*sqrt(dx^2+dy^2)   (== (dx+dy)-min(dx,dy))
// IEEE ops so rounding matches XLA regardless of nvcc fast-math flags.
__device__ __forceinline__ float heur_part(int r, int c, int gr, int gc) {
    int d0 = r - gr; if (d0 < 0) d0 = -d0;
    int d1 = c - gc; if (d1 < 0) d1 = -d1;
    int mx = d0 > d1 ? d0 : d1;
    float euc = __fsqrt_rn((float)(d0 * d0 + d1 * d1));
    return __fadd_rn((float)mx, __fmul_rn(0.001f, euc));
}

// dynamic smem layout:
//  key   : 4096 f32  (f = 0.5g+0.5h if open, +inf otherwise)
//  g     : 4096 f32
//  gpc   : 4096 f32  (invariant: gpc[i] == fadd(g[i], cost[i]))
//  keyh  : 4096 f32  (heur + cost, precomputed)
//  cost  : 4096 f32
//  par   : 4096 u16
//  obstw/smw/histw/pathw : 4 x 128 u32
#define SMEM_BYTES (5 * 4096 * 4 + 4096 * 2 + 4 * 128 * 4)

extern __shared__ unsigned char dynsmem[];

__global__ __launch_bounds__(128, 1)
void astar_kernel(const float* __restrict__ cost_all,
                  const float* __restrict__ start_all,
                  const float* __restrict__ goal_all,
                  const float* __restrict__ obst_all,
                  float* __restrict__ out)
{
    const int HW = 4096;
    const int STEPS = 409;               // int(0.1 * 64 * 64)

    float* key            = (float*)dynsmem;
    float* g_arr          = key   + 4096;
    float* gpc            = g_arr + 4096;
    float* keyh           = gpc   + 4096;
    float* cost_s         = keyh  + 4096;
    unsigned short* par   = (unsigned short*)(cost_s + 4096);
    unsigned* obstw       = (unsigned*)(par + 4096);
    unsigned* smw         = obstw + 128;
    unsigned* histw       = smw   + 128;
    unsigned* pathw       = histw + 128;

    __shared__ int s_goal, s_start;

    const int b    = blockIdx.x;
    const int tid  = threadIdx.x;
    const int lane = tid & 31;
    const int wid  = tid >> 5;

    // ---------------- init: zero bit words, then vectorized pass 1 ----------------
    obstw[tid] = 0u; smw[tid] = 0u; histw[tid] = 0u; pathw[tid] = 0u;
    __syncthreads();

    {
        const float4* cost4  = (const float4*)(cost_all  + b * HW);
        const float4* start4 = (const float4*)(start_all + b * HW);
        const float4* goal4  = (const float4*)(goal_all  + b * HW);
        const float4* obst4  = (const float4*)(obst_all  + b * HW);
        float4* cost_s4 = (float4*)cost_s;
        float4* gpc4    = (float4*)gpc;
        float4* key4    = (float4*)key;
        float4* g4      = (float4*)g_arr;
        const float inf = __uint_as_float(INFB);
        for (int i4 = tid; i4 < 1024; i4 += 128) {
            int base = i4 << 2;
            float4 gl = goal4[i4], st = start4[i4], ob = obst4[i4];
            if (gl.x > 0.5f) s_goal = base;     if (gl.y > 0.5f) s_goal = base + 1;
            if (gl.z > 0.5f) s_goal = base + 2; if (gl.w > 0.5f) s_goal = base + 3;
            if (st.x > 0.5f) s_start = base;     if (st.y > 0.5f) s_start = base + 1;
            if (st.z > 0.5f) s_start = base + 2; if (st.w > 0.5f) s_start = base + 3;
            unsigned nib = (ob.x > 0.5f ? 1u : 0u) | (ob.y > 0.5f ? 2u : 0u)
                         | (ob.z > 0.5f ? 4u : 0u) | (ob.w > 0.5f ? 8u : 0u);
            atomicOr(&obstw[base >> 5], nib << (base & 31));
            float4 cv = cost4[i4];
            cost_s4[i4] = cv;
            gpc4[i4]    = cv;                     // g=0: fadd(0,cost)==cost exactly
            key4[i4]    = make_float4(inf, inf, inf, inf);
            g4[i4]      = make_float4(0.f, 0.f, 0.f, 0.f);
        }
    }
    __syncthreads();

    const int goal_idx  = s_goal;
    const int start_idx = s_start;
    const int gr = goal_idx >> 6, gc = goal_idx & 63;

    // ---------------- init pass 2: precompute keyh, parents ----------------
    {
        float4*  keyh4 = (float4*)keyh;
        ushort4* par4  = (ushort4*)par;
        const unsigned short gp = (unsigned short)goal_idx;
        for (int i4 = tid; i4 < 1024; i4 += 128) {
            int base = i4 << 2;
            float4 cv = ((const float4*)cost_s)[i4];
            float4 kh;
            kh.x = __fadd_rn(heur_part(base >> 6, base & 63, gr, gc), cv.x);
            kh.y = __fadd_rn(heur_part((base + 1) >> 6, (base + 1) & 63, gr, gc), cv.y);
            kh.z = __fadd_rn(heur_part((base + 2) >> 6, (base + 2) & 63, gr, gc), cv.z);
            kh.w = __fadd_rn(heur_part((base + 3) >> 6, (base + 3) & 63, gr, gc), cv.w);
            keyh4[i4] = kh;
            par4[i4]  = make_ushort4(gp, gp, gp, gp);
        }
    }
    __syncthreads();

    // ---------------- single-warp sequential search ----------------
    if (wid == 0) {
        // open the start cell
        unsigned rm0 = INFB, rm1 = INFB;            // per-row mins: lane owns rows lane, lane+32
        {
            float f0 = 0.5f * keyh[start_idx];       // g=0: exact
            if (lane == 0) {
                key[start_idx] = f0;
                smw[start_idx >> 5] |= 1u << (start_idx & 31);
            }
            int srow = start_idx >> 6;
            if (lane == (srow & 31)) {
                if (srow < 32) rm0 = __float_as_uint(f0);
                else           rm1 = __float_as_uint(f0);
            }
        }
        __syncwarp();
        unsigned m = __reduce_min_sync(FULLMASK, rm0 < rm1 ? rm0 : rm1);

        for (int step = 0; step < STEPS; ++step) {
            // ---- A: resolve argmin location (m already known) with first-index tie-break
            unsigned b0 = __ballot_sync(FULLMASK, rm0 == m);
            unsigned b1 = __ballot_sync(FULLMASK, rm1 == m);
            int r = b0 ? (__ffs(b0) - 1) : (__ffs(b1) + 31);
            unsigned k0 = __float_as_uint(key[(r << 6) + lane]);
            unsigned k1 = __float_as_uint(key[(r << 6) + 32 + lane]);
            unsigned c0 = __ballot_sync(FULLMASK, k0 == m);
            unsigned c1 = __ballot_sync(FULLMASK, k1 == m);
            int c = c0 ? (__ffs(c0) - 1) : (__ffs(c1) + 31);
            const int sel = (r << 6) + c;

            // ---- B: close + expand
            if (lane == 0)
                histw[sel >> 5] |= 1u << (sel & 31);       // only writer of histw
            if (sel == goal_idx) break;                     // solve step: expansion provably
                                                            // cannot affect hist/path outputs
            if (lane == 0) {
                atomicAnd(&smw[sel >> 5], ~(1u << (sel & 31)));
                key[sel] = __uint_as_float(INFB);
            }
            float g2 = gpc[sel];     // == fadd(g[sel], cost[sel]) by invariant; broadcast LDS

            unsigned kb = INFB; int nrow = -99;
            if (lane < 8) {
                int idx9 = lane + (lane >= 4);              // 0..8 skipping center
                int nr = r + idx9 / 3 - 1;
                int nc = c + idx9 % 3 - 1;
                if (nr >= 0 && nr < 64 && nc >= 0 && nc < 64) {
                    int n = (nr << 6) + nc;
                    unsigned bm = 1u << (n & 31);
                    if (obstw[n >> 5] & bm) {
                        bool smv = smw[n >> 5] & bm;
                        bool hv  = histw[n >> 5] & bm;
                        if ((!smv && !hv) || (smv && g_arr[n] > g2)) {
                            g_arr[n] = g2;
                            gpc[n]   = __fadd_rn(g2, cost_s[n]);   // maintain invariant
                            float kn = __fadd_rn(0.5f * g2, 0.5f * keyh[n]);
                            key[n] = kn;
                            par[n] = (unsigned short)sel;
                            atomicOr(&smw[n >> 5], bm);
                            kb = __float_as_uint(kn); nrow = nr;   // updates only DECREASE keys
                        }
                    }
                }
            }
            // ---- C: FOUR independent reduxes, fully pipelined.
            //  mup/mdn: new keys for rows r-1/r+1 (fold-in; monotone decrease)
            //  mrow: exact row-r min from phase-A registers (sel masked) + same-row new keys
            //  mrem: global min over all rows EXCEPT r, from PRE-FOLD registers
            //  next m = min(mrem, mup, mdn, mrow)  — replaces next step's serial redux
            unsigned vup = (nrow == r - 1) ? kb : INFB;
            unsigned vdn = (nrow == r + 1) ? kb : INFB;
            unsigned vrw = (nrow == r)     ? kb : INFB;
            unsigned mk0 = (c < 32  && lane == c)        ? INFB : k0;
            unsigned mk1 = (c >= 32 && lane == (c - 32)) ? INFB : k1;
            unsigned mrv = mk0 < mk1 ? mk0 : mk1;
            mrv = mrv < vrw ? mrv : vrw;
            unsigned q0 = (lane == r)      ? INFB : rm0;   // lane<32: matches only if r<32
            unsigned q1 = (lane == r - 32) ? INFB : rm1;   // matches only if r>=32
            unsigned mup  = __reduce_min_sync(FULLMASK, vup);
            unsigned mdn  = __reduce_min_sync(FULLMASK, vdn);
            unsigned mrow = __reduce_min_sync(FULLMASK, mrv);
            unsigned mrem = __reduce_min_sync(FULLMASK, q0 < q1 ? q0 : q1);
            unsigned t0 = mrem < mrow ? mrem : mrow;
            unsigned t1 = mup  < mdn  ? mup  : mdn;
            m = t0 < t1 ? t0 : t1;
            // fold updates into owner-lane row mins
            if (r > 0 && lane == ((r - 1) & 31)) {
                if (r - 1 < 32) { if (mup < rm0) rm0 = mup; }
                else            { if (mup < rm1) rm1 = mup; }
            }
            if (r < 63 && lane == ((r + 1) & 31)) {
                if (r + 1 < 32) { if (mdn < rm0) rm0 = mdn; }
                else            { if (mdn < rm1) rm1 = mdn; }
            }
            if (lane == (r & 31)) {
                if (r < 32) rm0 = mrow; else rm1 = mrow;
            }
            __syncwarp();   // order this step's STS before next step's key-row LDS
        }

        // ---- backtrack (lane 0): deterministic chase repeats after any revisit,
        // so stop at the first already-marked node; cap 408 == reference t_stop bound.
        if (lane == 0) {
            pathw[goal_idx >> 5] |= 1u << (goal_idx & 31);
            int loc = par[goal_idx];
            #pragma unroll 1
            for (int i = 0; i < STEPS - 1; ++i) {
                unsigned bm = 1u << (loc & 31);
                if (pathw[loc >> 5] & bm) break;
                pathw[loc >> 5] |= bm;
                loc = par[loc];
            }
        }
    }
    __syncthreads();

    // ---------------- outputs: hist (B,1,64,64) then path (B,1,64,64) ----------------
    {
        float4* hist4 = (float4*)(out + b * HW);
        float4* path4 = (float4*)(out + 16 * HW + b * HW);
        for (int i4 = tid; i4 < 1024; i4 += 128) {
            int base = i4 << 2;
            unsigned hw = histw[base >> 5] >> (base & 31);
            unsigned pw = pathw[base >> 5] >> (base & 31);
            hist4[i4] = make_float4((hw & 1) ? 1.f : 0.f, (hw & 2) ? 1.f : 0.f,
                                    (hw & 4) ? 1.f : 0.f, (hw & 8) ? 1.f : 0.f);
            path4[i4] = make_float4((pw & 1) ? 1.f : 0.f, (pw & 2) ? 1.f : 0.f,
                                    (pw & 4) ? 1.f : 0.f, (pw & 8) ? 1.f : 0.f);
        }
    }
}

extern "C" void kernel_launch(void* const* d_in, const int* in_sizes, int n_in,
                              void* d_out, int out_size) {
    const float* cost  = (const float*)d_in[0];
    const float* start = (const float*)d_in[1];
    const float* goal  = (const float*)d_in[2];
    const float* obst  = (const float*)d_in[3];
    cudaFuncSetAttribute(astar_kernel,
                         cudaFuncAttributeMaxDynamicSharedMemorySize, SMEM_BYTES);
    astar_kernel<<<16, 128, SMEM_BYTES>>>(cost, start, goal, obst, (float*)d_out);
}